// round 17
// baseline (speedup 1.0000x reference)
#include <cuda_runtime.h>
#include <cuda_bf16.h>
#include <cuda_fp16.h>
#include <cstdint>

#define N_NODES 50000
#define N_EDGES 800000
#define D_IN    256
#define D_OUT   128
#define EPSV    1e-9f

// Scratch (allocation-free rule: __device__ globals)
__device__ __half g_Z [(size_t)N_NODES * D_OUT];  // Z = feat @ W1   [N, 128] (fp16)
__device__ float  g_H1[(size_t)N_NODES * D_OUT];  // H1 = A @ Z      [N, 128] (fp32)
// W pre-transposed to [n][k] and bf16-split: B[n][k] = W[k][n] (n<128 -> W0, else W1)
__device__ __nv_bfloat16 g_Whi[256 * 256];
__device__ __nv_bfloat16 g_Wlo[256 * 256];

__device__ __forceinline__ uint32_t smem_u32(const void* p) {
    uint32_t a;
    asm("{ .reg .u64 t; cvta.to.shared.u64 t, %1; cvt.u32.u64 %0, t; }" : "=r"(a) : "l"(p));
    return a;
}

// ---------------- prep: W split + zero H1 in one launch ----------------
__global__ void prep_kernel(const float* __restrict__ W0, const float* __restrict__ W1) {
    int blk = blockIdx.x;
    if (blk < 256) {
        int id = blk * 256 + threadIdx.x;      // 65536
        int n = id >> 8, k = id & 255;
        float w = (n < 128) ? __ldg(W0 + k * 128 + n) : __ldg(W1 + k * 128 + (n - 128));
        __nv_bfloat16 h = __float2bfloat16(w);
        float lo = w - __bfloat162float(h);
        g_Whi[n * 256 + k] = h;
        g_Wlo[n * 256 + k] = __float2bfloat16(lo);
    } else {
        int idx = (blk - 256) * 256 + threadIdx.x;
        const int total = N_NODES * D_OUT / 4;
        if (idx < total)
            reinterpret_cast<float4*>(g_H1)[idx] = make_float4(0.f, 0.f, 0.f, 0.f);
    }
}

// ---------------- HMMA GEMM halves (templated on H) --------------------------------
// H=0 -> out[:, :128] = LN(relu(feat@W0+b0)); H=1 -> g_Z = feat@W1 (fp16 raw).
#define MT   128
#define KCH  64
#define ASTR 72
#define A_HI_OFF 0
#define A_LO_OFF (MT * ASTR * 2)                 // 18432
#define B_HI_OFF (A_LO_OFF + MT * ASTR * 2)      // 36864
#define B_LO_OFF (B_HI_OFF + 128 * ASTR * 2)     // 55296
#define HMMA_SMEM (B_LO_OFF + 128 * ASTR * 2)    // 73728 B -> 2 CTAs/SM
#define HMMA_SMEM_BIG (120 * 1024)               // forces 1 CTA/SM; frees RF for spmm co-residency

__device__ __forceinline__ void ldm_x4(uint32_t* r, uint32_t addr) {
    asm volatile("ldmatrix.sync.aligned.m8n8.x4.shared.b16 {%0,%1,%2,%3}, [%4];"
                 : "=r"(r[0]), "=r"(r[1]), "=r"(r[2]), "=r"(r[3]) : "r"(addr));
}
__device__ __forceinline__ void ldm_x2(uint32_t* r, uint32_t addr) {
    asm volatile("ldmatrix.sync.aligned.m8n8.x2.shared.b16 {%0,%1}, [%2];"
                 : "=r"(r[0]), "=r"(r[1]) : "r"(addr));
}
__device__ __forceinline__ void mma_bf16(float* c, const uint32_t* a, const uint32_t* b) {
    asm volatile("mma.sync.aligned.m16n8k16.row.col.f32.bf16.bf16.f32 "
                 "{%0,%1,%2,%3}, {%4,%5,%6,%7}, {%8,%9}, {%0,%1,%2,%3};"
                 : "+f"(c[0]), "+f"(c[1]), "+f"(c[2]), "+f"(c[3])
                 : "r"(a[0]), "r"(a[1]), "r"(a[2]), "r"(a[3]), "r"(b[0]), "r"(b[1]));
}

template <int H>
__global__ void __launch_bounds__(256, 2)
gemm_hmma_kernel(const float* __restrict__ feat,
                 const float* __restrict__ b0, const float* __restrict__ scale0,
                 const float* __restrict__ offset0, float* __restrict__ out)
{
    extern __shared__ char smem[];
    const uint32_t sb = smem_u32(smem);
    const int tid  = threadIdx.x;
    const int warp = tid >> 5;
    const int lane = tid & 31;
    const int mw   = warp >> 2;   // 0..1
    const int nw   = warp & 3;    // 0..3
    const int row0 = blockIdx.x * MT;

    float acc[4][4][4];
#pragma unroll
    for (int mi = 0; mi < 4; ++mi)
#pragma unroll
        for (int ni = 0; ni < 4; ++ni)
#pragma unroll
            for (int j = 0; j < 4; ++j) acc[mi][ni][j] = 0.f;

    const int a_row  = mw * 64 + (lane & 15);
    const int a_coff = (lane >> 4) * 8;
    const int b_row  = nw * 32 + (lane & 7);
    const int b_koff = ((lane >> 3) & 1) * 8;
    const __nv_bfloat16* Whi_h = g_Whi + (size_t)H * 128 * 256;
    const __nv_bfloat16* Wlo_h = g_Wlo + (size_t)H * 128 * 256;

    for (int kc = 0; kc < 4; ++kc) {
#pragma unroll
        for (int j = 0; j < 8; ++j) {
            int i = tid + j * 256;
            int r = i >> 4, c4 = (i & 15) * 4;
            int grow = row0 + r;
            float4 v = make_float4(0.f, 0.f, 0.f, 0.f);
            if (grow < N_NODES)
                v = *reinterpret_cast<const float4*>(feat + (size_t)grow * D_IN + kc * KCH + c4);
            __nv_bfloat16 h0 = __float2bfloat16(v.x), h1 = __float2bfloat16(v.y);
            __nv_bfloat16 h2 = __float2bfloat16(v.z), h3 = __float2bfloat16(v.w);
            __nv_bfloat16 l0 = __float2bfloat16(v.x - __bfloat162float(h0));
            __nv_bfloat16 l1 = __float2bfloat16(v.y - __bfloat162float(h1));
            __nv_bfloat16 l2 = __float2bfloat16(v.z - __bfloat162float(h2));
            __nv_bfloat16 l3 = __float2bfloat16(v.w - __bfloat162float(h3));
            unsigned long long ph =
                (unsigned long long)__bfloat16_as_ushort(h0)
              | ((unsigned long long)__bfloat16_as_ushort(h1) << 16)
              | ((unsigned long long)__bfloat16_as_ushort(h2) << 32)
              | ((unsigned long long)__bfloat16_as_ushort(h3) << 48);
            unsigned long long pl =
                (unsigned long long)__bfloat16_as_ushort(l0)
              | ((unsigned long long)__bfloat16_as_ushort(l1) << 16)
              | ((unsigned long long)__bfloat16_as_ushort(l2) << 32)
              | ((unsigned long long)__bfloat16_as_ushort(l3) << 48);
            size_t off = ((size_t)r * ASTR + c4) * 2;
            *reinterpret_cast<unsigned long long*>(smem + A_HI_OFF + off) = ph;
            *reinterpret_cast<unsigned long long*>(smem + A_LO_OFF + off) = pl;
        }
#pragma unroll
        for (int j = 0; j < 4; ++j) {
            int i = tid + j * 256;
            int n = i >> 3, ch = i & 7;
            size_t off = ((size_t)n * ASTR + ch * 8) * 2;
            *reinterpret_cast<uint4*>(smem + B_HI_OFF + off) =
                *reinterpret_cast<const uint4*>(Whi_h + n * 256 + kc * KCH + ch * 8);
            *reinterpret_cast<uint4*>(smem + B_LO_OFF + off) =
                *reinterpret_cast<const uint4*>(Wlo_h + n * 256 + kc * KCH + ch * 8);
        }
        __syncthreads();

#pragma unroll
        for (int kk = 0; kk < 4; ++kk) {
            uint32_t a_hi[4][4], a_lo[4][4], b[4][2];
            uint32_t acol = kk * 16 + a_coff;
            uint32_t bcol = kk * 16 + b_koff;
#pragma unroll
            for (int mi = 0; mi < 4; ++mi)
                ldm_x4(a_hi[mi], sb + A_HI_OFF + ((a_row + mi * 16) * ASTR + acol) * 2);
#pragma unroll
            for (int ni = 0; ni < 4; ++ni)
                ldm_x2(b[ni], sb + B_HI_OFF + ((b_row + ni * 8) * ASTR + bcol) * 2);
#pragma unroll
            for (int mi = 0; mi < 4; ++mi)
#pragma unroll
                for (int ni = 0; ni < 4; ++ni) mma_bf16(acc[mi][ni], a_hi[mi], b[ni]);
#pragma unroll
            for (int mi = 0; mi < 4; ++mi)
                ldm_x4(a_lo[mi], sb + A_LO_OFF + ((a_row + mi * 16) * ASTR + acol) * 2);
#pragma unroll
            for (int mi = 0; mi < 4; ++mi)
#pragma unroll
                for (int ni = 0; ni < 4; ++ni) mma_bf16(acc[mi][ni], a_lo[mi], b[ni]);
#pragma unroll
            for (int ni = 0; ni < 4; ++ni)
                ldm_x2(b[ni], sb + B_LO_OFF + ((b_row + ni * 8) * ASTR + bcol) * 2);
#pragma unroll
            for (int mi = 0; mi < 4; ++mi)
#pragma unroll
                for (int ni = 0; ni < 4; ++ni) mma_bf16(acc[mi][ni], a_hi[mi], b[ni]);
        }
        __syncthreads();
    }

    const int rloc  = mw * 64 + (lane >> 2);
    const int cbase = nw * 32 + 2 * (lane & 3);

    if (H == 1) {
#pragma unroll
        for (int mi = 0; mi < 4; ++mi) {
            int r0 = row0 + rloc + mi * 16;
            int r1 = r0 + 8;
#pragma unroll
            for (int ni = 0; ni < 4; ++ni) {
                int col = cbase + ni * 8;
                if (r0 < N_NODES)
                    *reinterpret_cast<__half2*>(g_Z + (size_t)r0 * 128 + col) =
                        __floats2half2_rn(acc[mi][ni][0], acc[mi][ni][1]);
                if (r1 < N_NODES)
                    *reinterpret_cast<__half2*>(g_Z + (size_t)r1 * 128 + col) =
                        __floats2half2_rn(acc[mi][ni][2], acc[mi][ni][3]);
            }
        }
        return;
    }

    // f0 path: LN(relu(D + b0)) -> out[:, :128]
    float2* red = reinterpret_cast<float2*>(smem);
    if (tid < 128) red[tid] = make_float2(0.f, 0.f);
    __syncthreads();

#pragma unroll
    for (int mi = 0; mi < 4; ++mi) {
        float s0 = 0.f, q0 = 0.f, s1 = 0.f, q1 = 0.f;
#pragma unroll
        for (int ni = 0; ni < 4; ++ni) {
            int col = cbase + ni * 8;
            float bx = __ldg(b0 + col), by = __ldg(b0 + col + 1);
            float v0 = fmaxf(acc[mi][ni][0] + bx, 0.f);
            float v1 = fmaxf(acc[mi][ni][1] + by, 0.f);
            float v2 = fmaxf(acc[mi][ni][2] + bx, 0.f);
            float v3 = fmaxf(acc[mi][ni][3] + by, 0.f);
            acc[mi][ni][0] = v0; acc[mi][ni][1] = v1;
            acc[mi][ni][2] = v2; acc[mi][ni][3] = v3;
            s0 += v0 + v1; q0 += v0 * v0 + v1 * v1;
            s1 += v2 + v3; q1 += v2 * v2 + v3 * v3;
        }
#pragma unroll
        for (int off = 1; off < 4; off <<= 1) {
            s0 += __shfl_xor_sync(0xffffffffu, s0, off);
            q0 += __shfl_xor_sync(0xffffffffu, q0, off);
            s1 += __shfl_xor_sync(0xffffffffu, s1, off);
            q1 += __shfl_xor_sync(0xffffffffu, q1, off);
        }
        if ((lane & 3) == 0) {
            atomicAdd(&red[rloc + mi * 16].x, s0);
            atomicAdd(&red[rloc + mi * 16].y, q0);
            atomicAdd(&red[rloc + mi * 16 + 8].x, s1);
            atomicAdd(&red[rloc + mi * 16 + 8].y, q1);
        }
    }
    __syncthreads();

#pragma unroll
    for (int mi = 0; mi < 4; ++mi) {
        int l0 = rloc + mi * 16, l1 = l0 + 8;
        int r0 = row0 + l0, r1 = row0 + l1;
        float2 sq0 = red[l0], sq1 = red[l1];
        float m0 = sq0.x * (1.f / 128.f);
        float i0 = rsqrtf(sq0.y * (1.f / 128.f) - m0 * m0 + EPSV);
        float m1 = sq1.x * (1.f / 128.f);
        float i1 = rsqrtf(sq1.y * (1.f / 128.f) - m1 * m1 + EPSV);
#pragma unroll
        for (int ni = 0; ni < 4; ++ni) {
            int col = cbase + ni * 8;
            float sx = __ldg(scale0 + col), sy = __ldg(scale0 + col + 1);
            float ox = __ldg(offset0 + col), oy = __ldg(offset0 + col + 1);
            if (r0 < N_NODES)
                *reinterpret_cast<float2*>(out + (size_t)r0 * 256 + col) =
                    make_float2((acc[mi][ni][0] - m0) * i0 * sx + ox,
                                (acc[mi][ni][1] - m0) * i0 * sy + oy);
            if (r1 < N_NODES)
                *reinterpret_cast<float2*>(out + (size_t)r1 * 256 + col) =
                    make_float2((acc[mi][ni][2] - m1) * i1 * sx + ox,
                                (acc[mi][ni][3] - m1) * i1 * sy + oy);
        }
    }
}

// ---------------- SpMM: warp owns 32 edges; fp16 gather, fp32 RED --------------------
#define EPW 32
__global__ void __launch_bounds__(256)
spmm_kernel(const int* __restrict__ erow, const int* __restrict__ ecol,
            const float* __restrict__ eval)
{
    const int warp_id = blockIdx.x * 8 + (threadIdx.x >> 5);
    const int lane = threadIdx.x & 31;
    const int base = warp_id * EPW;
    if (base >= N_EDGES) return;

    int   my_r = __ldg(erow + base + lane);
    int   my_c = __ldg(ecol + base + lane);
    float my_v = __ldg(eval + base + lane);

    const __half* Zl  = g_Z  + lane * 4;
    float*        H1l = g_H1 + lane * 4;

#pragma unroll
    for (int jo = 0; jo < EPW; jo += 8) {
        int c[8], r[8]; float v[8];
#pragma unroll
        for (int t = 0; t < 8; ++t) {
            c[t] = __shfl_sync(0xffffffffu, my_c, jo + t);
            r[t] = __shfl_sync(0xffffffffu, my_r, jo + t);
            v[t] = __shfl_sync(0xffffffffu, my_v, jo + t);
        }
        uint2 z[8];
#pragma unroll
        for (int t = 0; t < 8; ++t)
            z[t] = *reinterpret_cast<const uint2*>(Zl + (size_t)c[t] * 128);
#pragma unroll
        for (int t = 0; t < 8; ++t) {
            float2 f01 = __half22float2(*reinterpret_cast<__half2*>(&z[t].x));
            float2 f23 = __half22float2(*reinterpret_cast<__half2*>(&z[t].y));
            asm volatile("red.global.add.v4.f32 [%0], {%1, %2, %3, %4};"
                         :: "l"(H1l + (size_t)r[t] * 128),
                            "f"(v[t] * f01.x), "f"(v[t] * f01.y),
                            "f"(v[t] * f23.x), "f"(v[t] * f23.y) : "memory");
        }
    }
}

// ---------------- f1 epilogue: out[:, 128:] = LN(relu(H1 + b1)) ----------------
__global__ void __launch_bounds__(256)
ln1_kernel(const float* __restrict__ b1, const float* __restrict__ scale1,
           const float* __restrict__ offset1, float* __restrict__ out)
{
    int row = blockIdx.x * 8 + (threadIdx.x >> 5);
    if (row >= N_NODES) return;
    int lane = threadIdx.x & 31;
    float4 h = *reinterpret_cast<const float4*>(g_H1 + (size_t)row * 128 + lane * 4);
    float4 b = *reinterpret_cast<const float4*>(b1 + lane * 4);
    h.x = fmaxf(h.x + b.x, 0.f);
    h.y = fmaxf(h.y + b.y, 0.f);
    h.z = fmaxf(h.z + b.z, 0.f);
    h.w = fmaxf(h.w + b.w, 0.f);
    float s = h.x + h.y + h.z + h.w;
    float q = h.x * h.x + h.y * h.y + h.z * h.z + h.w * h.w;
#pragma unroll
    for (int off = 16; off > 0; off >>= 1) {
        s += __shfl_xor_sync(0xffffffffu, s, off);
        q += __shfl_xor_sync(0xffffffffu, q, off);
    }
    float mean = s * (1.f / 128.f);
    float var  = q * (1.f / 128.f) - mean * mean;
    float inv  = rsqrtf(var + EPSV);
    float4 sc = *reinterpret_cast<const float4*>(scale1 + lane * 4);
    float4 of = *reinterpret_cast<const float4*>(offset1 + lane * 4);
    float4 w;
    w.x = (h.x - mean) * inv * sc.x + of.x;
    w.y = (h.y - mean) * inv * sc.y + of.y;
    w.z = (h.z - mean) * inv * sc.z + of.z;
    w.w = (h.w - mean) * inv * sc.w + of.w;
    *reinterpret_cast<float4*>(out + (size_t)row * 256 + 128 + lane * 4) = w;
}

extern "C" void kernel_launch(void* const* d_in, const int* in_sizes, int n_in,
                              void* d_out, int out_size)
{
    const float* feat    = (const float*)d_in[0];
    const float* W0      = (const float*)d_in[1];
    const float* b0      = (const float*)d_in[2];
    const float* scale0  = (const float*)d_in[3];
    const float* offset0 = (const float*)d_in[4];
    const float* W1      = (const float*)d_in[5];
    const float* b1      = (const float*)d_in[6];
    const float* scale1  = (const float*)d_in[7];
    const float* offset1 = (const float*)d_in[8];
    const int*   erow    = (const int*)d_in[9];
    const int*   ecol    = (const int*)d_in[10];
    const float* eval    = (const float*)d_in[11];
    float* out = (float*)d_out;

    // f0 half gets surplus smem -> 1 CTA/SM -> half the RF left free so spmm
    // CTAs co-reside on the same SMs (tensor-pipe + L2-pipe overlap).
    cudaFuncSetAttribute(gemm_hmma_kernel<0>,
                         cudaFuncAttributeMaxDynamicSharedMemorySize, HMMA_SMEM_BIG);
    cudaFuncSetAttribute(gemm_hmma_kernel<1>,
                         cudaFuncAttributeMaxDynamicSharedMemorySize, HMMA_SMEM);

    cudaStream_t s2;
    cudaEvent_t ev_fork, ev_join;
    cudaStreamCreateWithFlags(&s2, cudaStreamNonBlocking);
    cudaEventCreateWithFlags(&ev_fork, cudaEventDisableTiming);
    cudaEventCreateWithFlags(&ev_join, cudaEventDisableTiming);

    const int GRID_T = (N_NODES + MT - 1) / MT;   // 391

    // default stream: prep -> Z-gemm (gates spmm)
    prep_kernel<<<256 + (N_NODES * D_OUT / 4 + 255) / 256, 256>>>(W0, W1);
    gemm_hmma_kernel<1><<<GRID_T, 256, HMMA_SMEM>>>(feat, b0, scale0, offset0, out);
    cudaEventRecord(ev_fork, 0);

    // fork: f0-gemm on s2 (1 CTA/SM), concurrent with spmm+ln1 on default stream
    cudaStreamWaitEvent(s2, ev_fork, 0);
    gemm_hmma_kernel<0><<<GRID_T, 256, HMMA_SMEM_BIG, s2>>>(feat, b0, scale0, offset0, out);
    cudaEventRecord(ev_join, s2);

    spmm_kernel<<<(N_EDGES / EPW + 7) / 8, 256>>>(erow, ecol, eval);
    ln1_kernel<<<(N_NODES + 7) / 8, 256>>>(b1, scale1, offset1, out);

    cudaStreamWaitEvent(0, ev_join, 0);
}